// round 12
// baseline (speedup 1.0000x reference)
#include <cuda_runtime.h>
#include <cuda_fp16.h>
#include <cstdint>

// SGConv: out = relu( (A @ ((x@W) * norm_src)) * norm_dst + b )
// B=4, N=16384, D=128, E=1048576
#define Bc   4
#define Nc   16384
#define Dc   128
#define BNc  (Bc * Nc)      // 65536 nodes
#define EMAX (1 << 20)
#define SCAN_BLOCKS 256     // 256 blocks x 256 threads = 65536
#define GEMM_BLOCKS (BNc / 128)   // 512
#define HIST_BLOCKS 512

// ---- scratch (static device globals; no allocation) ----
// NOTE: g_cnt/g_deg are zeroed at the END of k_scatter (state restoration for
// the next graph replay); module-load zero-init covers the first call.
__device__ float   g_y[(size_t)BNc * Dc];  // 32 MB: support = x@W, fp32
__device__ __half2 g_yh[(size_t)BNc * 64]; // 16 MB: (support*norm_src), fp16
__device__ float g_deg[BNc];
__device__ float g_norm[BNc];
__device__ int   g_cnt[BNc];
__device__ int   g_off[BNc + 1];
__device__ int   g_rank[EMAX];            // within-destination edge rank
__device__ int2  g_edge[EMAX];            // CSR-sorted (src, edge_val)
__device__ int   g_blksum_unused[1];      // (kept for layout stability)

// ---- packed f32x2 helpers (FFMA2 path; ptxas won't auto-fuse) ----
__device__ __forceinline__ unsigned long long pack2(float lo, float hi) {
    unsigned long long r;
    asm("mov.b64 %0, {%1, %2};" : "=l"(r) : "f"(lo), "f"(hi));
    return r;
}
__device__ __forceinline__ void unpack2(unsigned long long v, float& lo, float& hi) {
    asm("mov.b64 {%0, %1}, %2;" : "=f"(lo), "=f"(hi) : "l"(v));
}
__device__ __forceinline__ void fma2(unsigned long long& d, unsigned long long a,
                                     unsigned long long b) {
    asm("fma.rn.f32x2 %0, %1, %2, %0;" : "+l"(d) : "l"(a), "l"(b));
}

// ---------------------------------------------------------------------------
// Fused GEMM + histogram (heterogeneous grid).
// Blocks [0, GEMM_BLOCKS): g_y = x @ W (fp32; 128x128 tile, 8x8 thread tile,
//   packed f32x2 FMA).
// Blocks [GEMM_BLOCKS, GEMM_BLOCKS+HIST_BLOCKS): grid-stride histogram; also
//   records each edge's within-destination rank (atomicAdd return) so the
//   scatter kernel needs no atomics.
__global__ void __launch_bounds__(256) k_gemm_hist(
        const float* __restrict__ x, const float* __restrict__ W,
        const int* __restrict__ eb, const int* __restrict__ er,
        const float* __restrict__ ev, int E) {
    __shared__ float Xs[128][36];   // [m][k], padded
    __shared__ float Ws[32][128];   // [k][n]

    if (blockIdx.x >= GEMM_BLOCKS) {
        // -------- histogram path (grid-stride) --------
        int start = (blockIdx.x - GEMM_BLOCKS) * 256 + threadIdx.x;
        for (int e = start; e < E; e += HIST_BLOCKS * 256) {
            int dst = eb[e] * Nc + er[e];
            atomicAdd(&g_deg[dst], fabsf(ev[e]));
            g_rank[e] = atomicAdd(&g_cnt[dst], 1);
        }
        return;
    }

    // -------- GEMM path --------
    int tid  = threadIdx.x;
    int row0 = blockIdx.x * 128;
    int tx = tid & 15, ty = tid >> 4;
    int m0 = ty * 8, n0 = tx * 8;

    unsigned long long acc2[8][4];
#pragma unroll
    for (int i = 0; i < 8; i++)
#pragma unroll
        for (int j = 0; j < 4; j++) acc2[i][j] = 0ull;

    const float4* x4 = reinterpret_cast<const float4*>(x);
    const float4* W4 = reinterpret_cast<const float4*>(W);

    for (int kk = 0; kk < 128; kk += 32) {
#pragma unroll
        for (int q = 0; q < 4; q++) {
            int idx = tid + 256 * q;
            int r  = idx >> 3;
            int kq = idx & 7;
            float4 v = x4[(size_t)(row0 + r) * 32 + (kk >> 2) + kq];
            *reinterpret_cast<float4*>(&Xs[r][kq * 4]) = v;
        }
#pragma unroll
        for (int q = 0; q < 4; q++) {
            int idx = tid + 256 * q;
            int k  = idx >> 5;
            int n4 = idx & 31;
            float4 v = W4[(size_t)(kk + k) * 32 + n4];
            *reinterpret_cast<float4*>(&Ws[k][n4 * 4]) = v;
        }
        __syncthreads();

#pragma unroll
        for (int k = 0; k < 32; k++) {
            float4 b0 = *reinterpret_cast<const float4*>(&Ws[k][n0]);
            float4 b1 = *reinterpret_cast<const float4*>(&Ws[k][n0 + 4]);
            unsigned long long bp[4];
            bp[0] = pack2(b0.x, b0.y);
            bp[1] = pack2(b0.z, b0.w);
            bp[2] = pack2(b1.x, b1.y);
            bp[3] = pack2(b1.z, b1.w);
#pragma unroll
            for (int i = 0; i < 8; i++) {
                float a = Xs[m0 + i][k];
                unsigned long long a2 = pack2(a, a);
                fma2(acc2[i][0], a2, bp[0]);
                fma2(acc2[i][1], a2, bp[1]);
                fma2(acc2[i][2], a2, bp[2]);
                fma2(acc2[i][3], a2, bp[3]);
            }
        }
        __syncthreads();
    }

#pragma unroll
    for (int i = 0; i < 8; i++) {
        float o[8];
#pragma unroll
        for (int j = 0; j < 4; j++) unpack2(acc2[i][j], o[2 * j], o[2 * j + 1]);
        float* dst = &g_y[(size_t)(row0 + m0 + i) * 128 + n0];
        *reinterpret_cast<float4*>(dst)     = make_float4(o[0], o[1], o[2], o[3]);
        *reinterpret_cast<float4*>(dst + 4) = make_float4(o[4], o[5], o[6], o[7]);
    }
}

// ---------------------------------------------------------------------------
// Single-pass scan + norm + y-scaling.
// Each block redundantly computes ALL 256 block-sums of g_cnt (g_cnt is
// L2-resident at 256 KB, so the 64 MB aggregate read is ~6 us) -> no
// cross-block dependency, no extra launch. Then: local exclusive scan ->
// g_off, norm -> g_norm, and a grid-stride pass scaling y by norm_src with
// a single fp32->fp16 rounding into g_yh.
__global__ void __launch_bounds__(256) k_scan() {
    __shared__ int bs[256];
    __shared__ int sh[256];
    int t    = threadIdx.x;
    int wid  = t >> 5;
    int lane = t & 31;

    // --- all 256 chunk sums, computed by this block (8 warps x 32 chunks) ---
    for (int chunk = wid; chunk < 256; chunk += 8) {
        int s = 0;
#pragma unroll 8
        for (int q = lane; q < 256; q += 32) s += g_cnt[chunk * 256 + q];
#pragma unroll
        for (int off = 16; off > 0; off >>= 1)
            s += __shfl_down_sync(0xffffffffu, s, off);
        if (lane == 0) bs[chunk] = s;
    }
    __syncthreads();

    // --- inclusive scan of chunk sums (Hillis-Steele, 256 wide) ---
    for (int off = 1; off < 256; off <<= 1) {
        int u = (t >= off) ? bs[t - off] : 0;
        __syncthreads();
        bs[t] += u;
        __syncthreads();
    }
    int blkoff = (blockIdx.x > 0) ? bs[blockIdx.x - 1] : 0;
    if (blockIdx.x == 0 && t == 0) g_off[BNc] = bs[255];

    // --- local exclusive scan over this block's 256 nodes ---
    int i = blockIdx.x * 256 + t;
    int c = g_cnt[i];
    sh[t] = c;
    __syncthreads();
    for (int off = 1; off < 256; off <<= 1) {
        int u = (t >= off) ? sh[t - off] : 0;
        __syncthreads();
        sh[t] += u;
        __syncthreads();
    }
    g_off[i] = blkoff + sh[t] - c;     // exclusive prefix
    g_norm[i] = rsqrtf(g_deg[i] + 1e-6f);

    // --- y scaling: g_yh[j] = half2( g_y2[j] * norm(row) ), coalesced ---
    // norm recomputed from g_deg to avoid cross-block g_norm visibility.
    const float2* y2 = reinterpret_cast<const float2*>(g_y);
    int gtid = blockIdx.x * 256 + t;
    for (size_t j = gtid; j < (size_t)BNc * 64; j += SCAN_BLOCKS * 256) {
        int row = (int)(j >> 6);
        float nrm = rsqrtf(g_deg[row] + 1e-6f);
        float2 v = y2[j];
        g_yh[j] = __floats2half2_rn(v.x * nrm, v.y * nrm);
    }
}

// ---------------------------------------------------------------------------
// scatter edges into CSR order (atomic-free: precomputed rank); pack
// (src, raw edge_val) into ONE int2 store (one 32B sector per edge).
// Tail: restore g_cnt/g_deg to zero for the next graph replay.
__global__ void k_scatter(const int* __restrict__ eb, const int* __restrict__ er,
                          const int* __restrict__ ec, const float* __restrict__ ev,
                          int E) {
    int e = blockIdx.x * blockDim.x + threadIdx.x;
    if (e < E) {
        int b   = eb[e];
        int dst = b * Nc + er[e];
        int src = b * Nc + ec[e];
        int pos = g_off[dst] + g_rank[e];
        g_edge[pos] = make_int2(src, __float_as_int(ev[e]));
    }
    if (e < BNc) { g_cnt[e] = 0; g_deg[e] = 0.f; }
}

// ---------------------------------------------------------------------------
// SpMM + epilogue: one warp per destination node, inner loop unrolled x4.
// y is fp16 (half2), pre-scaled by norm_src: each lane covers 4 of 128 cols.
__global__ void __launch_bounds__(256) k_spmm(const float* __restrict__ bias,
                                              float* __restrict__ out) {
    int w    = (blockIdx.x * 256 + threadIdx.x) >> 5;
    int lane = threadIdx.x & 31;
    if (w >= BNc) return;

    int s = g_off[w];
    int e = g_off[w + 1];
    const uint2* y2 = reinterpret_cast<const uint2*>(g_yh);  // 32 uint2/row

    float4 acc = make_float4(0.f, 0.f, 0.f, 0.f);
    for (int base = s; base < e; base += 32) {
        int idx = base + lane;
        bool valid = idx < e;
        int   src = 0;
        float v   = 0.f;
        if (valid) {
            int2 p = g_edge[idx];
            src = p.x;
            v   = __int_as_float(p.y);
        }
        int m = e - base;
        if (m > 32) m = 32;
        int mp = (m + 3) & ~3;                  // pad to multiple of 4
        for (int j = 0; j < mp; j += 4) {
            int   s0 = __shfl_sync(0xffffffffu, src, j);
            int   s1 = __shfl_sync(0xffffffffu, src, j + 1);
            int   s2 = __shfl_sync(0xffffffffu, src, j + 2);
            int   s3 = __shfl_sync(0xffffffffu, src, j + 3);
            float v0 = __shfl_sync(0xffffffffu, v, j);
            float v1 = __shfl_sync(0xffffffffu, v, j + 1);
            float v2 = __shfl_sync(0xffffffffu, v, j + 2);
            float v3 = __shfl_sync(0xffffffffu, v, j + 3);
            uint2 r0 = y2[(size_t)s0 * 32 + lane];
            uint2 r1 = y2[(size_t)s1 * 32 + lane];
            uint2 r2 = y2[(size_t)s2 * 32 + lane];
            uint2 r3 = y2[(size_t)s3 * 32 + lane];
            float2 a0 = __half22float2(reinterpret_cast<const __half2&>(r0.x));
            float2 b0 = __half22float2(reinterpret_cast<const __half2&>(r0.y));
            float2 a1 = __half22float2(reinterpret_cast<const __half2&>(r1.x));
            float2 b1 = __half22float2(reinterpret_cast<const __half2&>(r1.y));
            float2 a2 = __half22float2(reinterpret_cast<const __half2&>(r2.x));
            float2 b2 = __half22float2(reinterpret_cast<const __half2&>(r2.y));
            float2 a3 = __half22float2(reinterpret_cast<const __half2&>(r3.x));
            float2 b3 = __half22float2(reinterpret_cast<const __half2&>(r3.y));
            acc.x = fmaf(v0, a0.x, acc.x);
            acc.y = fmaf(v0, a0.y, acc.y);
            acc.z = fmaf(v0, b0.x, acc.z);
            acc.w = fmaf(v0, b0.y, acc.w);
            acc.x = fmaf(v1, a1.x, acc.x);
            acc.y = fmaf(v1, a1.y, acc.y);
            acc.z = fmaf(v1, b1.x, acc.z);
            acc.w = fmaf(v1, b1.y, acc.w);
            acc.x = fmaf(v2, a2.x, acc.x);
            acc.y = fmaf(v2, a2.y, acc.y);
            acc.z = fmaf(v2, b2.x, acc.z);
            acc.w = fmaf(v2, b2.y, acc.w);
            acc.x = fmaf(v3, a3.x, acc.x);
            acc.y = fmaf(v3, a3.y, acc.y);
            acc.z = fmaf(v3, b3.x, acc.z);
            acc.w = fmaf(v3, b3.y, acc.w);
        }
    }

    float nrm = g_norm[w];
    float4 bv = reinterpret_cast<const float4*>(bias)[lane];
    float4 o;
    o.x = fmaxf(fmaf(acc.x, nrm, bv.x), 0.f);
    o.y = fmaxf(fmaf(acc.y, nrm, bv.y), 0.f);
    o.z = fmaxf(fmaf(acc.z, nrm, bv.z), 0.f);
    o.w = fmaxf(fmaf(acc.w, nrm, bv.w), 0.f);
    reinterpret_cast<float4*>(out)[(size_t)w * 32 + lane] = o;
}

// ---------------------------------------------------------------------------
extern "C" void kernel_launch(void* const* d_in, const int* in_sizes, int n_in,
                              void* d_out, int out_size) {
    const float* x  = (const float*)d_in[0];   // [B,N,D]
    const float* W  = (const float*)d_in[1];   // [D,D]
    const float* bb = (const float*)d_in[2];   // [D]
    const int*   eb = (const int*)d_in[3];     // [E]
    const int*   er = (const int*)d_in[4];     // [E]
    const int*   ec = (const int*)d_in[5];     // [E]
    const float* ev = (const float*)d_in[6];   // [E]
    int E = in_sizes[3];

    float* out = (float*)d_out;

    k_gemm_hist<<<GEMM_BLOCKS + HIST_BLOCKS, 256>>>(x, W, eb, er, ev, E);
    k_scan<<<SCAN_BLOCKS, 256>>>();
    k_scatter<<<(E + 255) / 256, 256>>>(eb, er, ec, ev, E);
    k_spmm<<<(BNc * 32) / 256, 256>>>(bb, out);
}

// round 13
// speedup vs baseline: 1.5191x; 1.5191x over previous
#include <cuda_runtime.h>
#include <cuda_fp16.h>
#include <cstdint>

// SGConv: out = relu( (A @ ((x@W) * norm_src)) * norm_dst + b )
// B=4, N=16384, D=128, E=1048576
#define Bc   4
#define Nc   16384
#define Dc   128
#define BNc  (Bc * Nc)      // 65536 nodes
#define EMAX (1 << 20)
#define SCAN_BLOCKS 256     // 256 blocks x 256 threads = 65536
#define GEMM_BLOCKS (BNc / 128)   // 512
#define HIST_BLOCKS 512

// ---- scratch (static device globals; no allocation) ----
// NOTE: g_cnt/g_deg are zeroed at the END of k_scatter (state restoration for
// the next graph replay); module-load zero-init covers the first call.
__device__ __half2 g_yh[(size_t)BNc * 64]; // 16 MB: support = x@W, fp16
__device__ float g_deg[BNc];
__device__ float g_norm[BNc];
__device__ int   g_cnt[BNc];
__device__ int   g_off[BNc + 1];
__device__ int   g_rank[EMAX];            // within-destination edge rank
__device__ int2  g_edge[EMAX];            // CSR-sorted (src, val*norm[src])
__device__ int   g_blksum[SCAN_BLOCKS];   // per-block count totals

// ---- packed f32x2 helpers (FFMA2 path; ptxas won't auto-fuse) ----
__device__ __forceinline__ unsigned long long pack2(float lo, float hi) {
    unsigned long long r;
    asm("mov.b64 %0, {%1, %2};" : "=l"(r) : "f"(lo), "f"(hi));
    return r;
}
__device__ __forceinline__ void unpack2(unsigned long long v, float& lo, float& hi) {
    asm("mov.b64 {%0, %1}, %2;" : "=f"(lo), "=f"(hi) : "l"(v));
}
__device__ __forceinline__ void fma2(unsigned long long& d, unsigned long long a,
                                     unsigned long long b) {
    asm("fma.rn.f32x2 %0, %1, %2, %0;" : "+l"(d) : "l"(a), "l"(b));
}

// ---------------------------------------------------------------------------
// Fused GEMM + histogram (heterogeneous grid).
// Blocks [0, GEMM_BLOCKS): g_yh = half(x @ W) (128x128 tile, 8x8 thread tile,
//   packed f32x2 FMA). Xs is stored TRANSPOSED [k][m] so the per-k A-column
//   read is 2x LDS.128 instead of 8x LDS.32 (mainloop: 4 shared loads/k
//   instead of 10; staging pays a 4-way STS conflict, amortized).
// Blocks [GEMM_BLOCKS, ...): grid-stride histogram; records each edge's
//   within-destination rank (atomicAdd return) so scatter needs no atomics.
__global__ void __launch_bounds__(256) k_gemm_hist(
        const float* __restrict__ x, const float* __restrict__ W,
        const int* __restrict__ eb, const int* __restrict__ er,
        const float* __restrict__ ev, int E) {
    __shared__ float Xs[32][132];   // [k][m], stride 132 keeps 16B alignment
    __shared__ float Ws[32][128];   // [k][n]

    if (blockIdx.x >= GEMM_BLOCKS) {
        // -------- histogram path (grid-stride) --------
        int start = (blockIdx.x - GEMM_BLOCKS) * 256 + threadIdx.x;
        for (int e = start; e < E; e += HIST_BLOCKS * 256) {
            int dst = eb[e] * Nc + er[e];
            atomicAdd(&g_deg[dst], fabsf(ev[e]));
            g_rank[e] = atomicAdd(&g_cnt[dst], 1);
        }
        return;
    }

    // -------- GEMM path --------
    int tid  = threadIdx.x;
    int row0 = blockIdx.x * 128;
    int tx = tid & 15, ty = tid >> 4;
    int m0 = ty * 8, n0 = tx * 8;

    unsigned long long acc2[8][4];
#pragma unroll
    for (int i = 0; i < 8; i++)
#pragma unroll
        for (int j = 0; j < 4; j++) acc2[i][j] = 0ull;

    const float4* x4 = reinterpret_cast<const float4*>(x);
    const float4* W4 = reinterpret_cast<const float4*>(W);

    for (int kk = 0; kk < 128; kk += 32) {
        // stage X tile transposed: thread reads float4 (4 k's, one m-row),
        // writes 4 scalars into Xs[k][m].
#pragma unroll
        for (int q = 0; q < 4; q++) {
            int idx = tid + 256 * q;
            int r  = idx >> 3;          // m within tile
            int kq = idx & 7;           // which float4 along k
            float4 v = x4[(size_t)(row0 + r) * 32 + (kk >> 2) + kq];
            Xs[kq * 4 + 0][r] = v.x;
            Xs[kq * 4 + 1][r] = v.y;
            Xs[kq * 4 + 2][r] = v.z;
            Xs[kq * 4 + 3][r] = v.w;
        }
#pragma unroll
        for (int q = 0; q < 4; q++) {
            int idx = tid + 256 * q;
            int k  = idx >> 5;
            int n4 = idx & 31;
            float4 v = W4[(size_t)(kk + k) * 32 + n4];
            *reinterpret_cast<float4*>(&Ws[k][n4 * 4]) = v;
        }
        __syncthreads();

#pragma unroll
        for (int k = 0; k < 32; k++) {
            float4 a0 = *reinterpret_cast<const float4*>(&Xs[k][m0]);
            float4 a1 = *reinterpret_cast<const float4*>(&Xs[k][m0 + 4]);
            float4 b0 = *reinterpret_cast<const float4*>(&Ws[k][n0]);
            float4 b1 = *reinterpret_cast<const float4*>(&Ws[k][n0 + 4]);
            unsigned long long bp[4];
            bp[0] = pack2(b0.x, b0.y);
            bp[1] = pack2(b0.z, b0.w);
            bp[2] = pack2(b1.x, b1.y);
            bp[3] = pack2(b1.z, b1.w);
            float av[8] = {a0.x, a0.y, a0.z, a0.w, a1.x, a1.y, a1.z, a1.w};
#pragma unroll
            for (int i = 0; i < 8; i++) {
                unsigned long long a2 = pack2(av[i], av[i]);
                fma2(acc2[i][0], a2, bp[0]);
                fma2(acc2[i][1], a2, bp[1]);
                fma2(acc2[i][2], a2, bp[2]);
                fma2(acc2[i][3], a2, bp[3]);
            }
        }
        __syncthreads();
    }

#pragma unroll
    for (int i = 0; i < 8; i++) {
        float o[8];
#pragma unroll
        for (int j = 0; j < 4; j++) unpack2(acc2[i][j], o[2 * j], o[2 * j + 1]);
        __half2 h0 = __floats2half2_rn(o[0], o[1]);
        __half2 h1 = __floats2half2_rn(o[2], o[3]);
        __half2 h2 = __floats2half2_rn(o[4], o[5]);
        __half2 h3 = __floats2half2_rn(o[6], o[7]);
        uint4 u;
        u.x = reinterpret_cast<const unsigned&>(h0);
        u.y = reinterpret_cast<const unsigned&>(h1);
        u.z = reinterpret_cast<const unsigned&>(h2);
        u.w = reinterpret_cast<const unsigned&>(h3);
        *reinterpret_cast<uint4*>(
            &g_yh[(size_t)(row0 + m0 + i) * 64 + (n0 >> 1)]) = u;
    }
}

// ---------------------------------------------------------------------------
// Parallel scan over g_cnt (65536 ints), fully coalesced.
// Phase A: per-block sums.
__global__ void __launch_bounds__(256) k_scanA() {
    __shared__ int sh[256];
    int t = threadIdx.x;
    int i = blockIdx.x * 256 + t;
    sh[t] = g_cnt[i];
    __syncthreads();
#pragma unroll
    for (int off = 128; off > 0; off >>= 1) {
        if (t < off) sh[t] += sh[t + off];
        __syncthreads();
    }
    if (t == 0) g_blksum[blockIdx.x] = sh[0];
}

// Phase BC (merged): every block redundantly scans the 256 block sums in smem
// to derive its own offset, then does its local exclusive scan + norm.
__global__ void __launch_bounds__(256) k_scanBC() {
    __shared__ int bs[256];
    __shared__ int sh[256];
    int t = threadIdx.x;

    bs[t] = g_blksum[t];
    __syncthreads();
    for (int off = 1; off < 256; off <<= 1) {
        int u = (t >= off) ? bs[t - off] : 0;
        __syncthreads();
        bs[t] += u;
        __syncthreads();
    }
    int blkoff = (blockIdx.x > 0) ? bs[blockIdx.x - 1] : 0;
    if (blockIdx.x == 0 && t == 0) g_off[BNc] = bs[255];

    int i = blockIdx.x * 256 + t;
    int c = g_cnt[i];
    sh[t] = c;
    __syncthreads();
    for (int off = 1; off < 256; off <<= 1) {
        int u = (t >= off) ? sh[t - off] : 0;
        __syncthreads();
        sh[t] += u;
        __syncthreads();
    }
    g_off[i] = blkoff + sh[t] - c;     // exclusive prefix
    g_norm[i] = rsqrtf(g_deg[i] + 1e-6f);
}

// ---------------------------------------------------------------------------
// scatter edges into CSR order (atomic-free: precomputed rank); fold the
// source-side norm into the edge value; pack (src, val) into ONE int2 store.
// Tail: restore g_cnt/g_deg to zero for the next graph replay.
__global__ void k_scatter(const int* __restrict__ eb, const int* __restrict__ er,
                          const int* __restrict__ ec, const float* __restrict__ ev,
                          int E) {
    int e = blockIdx.x * blockDim.x + threadIdx.x;
    if (e < E) {
        int b   = eb[e];
        int dst = b * Nc + er[e];
        int src = b * Nc + ec[e];
        int pos = g_off[dst] + g_rank[e];
        float v = ev[e] * g_norm[src];
        g_edge[pos] = make_int2(src, __float_as_int(v));
    }
    if (e < BNc) { g_cnt[e] = 0; g_deg[e] = 0.f; }
}

// ---------------------------------------------------------------------------
// SpMM + epilogue: one warp per destination node, inner loop unrolled x4.
// y is fp16 (half2): each lane covers 4 of 128 cols (8 B per edge per lane).
__global__ void __launch_bounds__(256) k_spmm(const float* __restrict__ bias,
                                              float* __restrict__ out) {
    int w    = (blockIdx.x * 256 + threadIdx.x) >> 5;
    int lane = threadIdx.x & 31;
    if (w >= BNc) return;

    int s = g_off[w];
    int e = g_off[w + 1];
    const uint2* y2 = reinterpret_cast<const uint2*>(g_yh);  // 32 uint2/row

    float4 acc = make_float4(0.f, 0.f, 0.f, 0.f);
    for (int base = s; base < e; base += 32) {
        int idx = base + lane;
        bool valid = idx < e;
        int   src = 0;
        float v   = 0.f;
        if (valid) {
            int2 p = g_edge[idx];
            src = p.x;
            v   = __int_as_float(p.y);
        }
        int m = e - base;
        if (m > 32) m = 32;
        int mp = (m + 3) & ~3;                  // pad to multiple of 4
        for (int j = 0; j < mp; j += 4) {
            int   s0 = __shfl_sync(0xffffffffu, src, j);
            int   s1 = __shfl_sync(0xffffffffu, src, j + 1);
            int   s2 = __shfl_sync(0xffffffffu, src, j + 2);
            int   s3 = __shfl_sync(0xffffffffu, src, j + 3);
            float v0 = __shfl_sync(0xffffffffu, v, j);
            float v1 = __shfl_sync(0xffffffffu, v, j + 1);
            float v2 = __shfl_sync(0xffffffffu, v, j + 2);
            float v3 = __shfl_sync(0xffffffffu, v, j + 3);
            uint2 r0 = y2[s0 * 32 + lane];
            uint2 r1 = y2[s1 * 32 + lane];
            uint2 r2 = y2[s2 * 32 + lane];
            uint2 r3 = y2[s3 * 32 + lane];
            float2 a0 = __half22float2(reinterpret_cast<const __half2&>(r0.x));
            float2 b0 = __half22float2(reinterpret_cast<const __half2&>(r0.y));
            float2 a1 = __half22float2(reinterpret_cast<const __half2&>(r1.x));
            float2 b1 = __half22float2(reinterpret_cast<const __half2&>(r1.y));
            float2 a2 = __half22float2(reinterpret_cast<const __half2&>(r2.x));
            float2 b2 = __half22float2(reinterpret_cast<const __half2&>(r2.y));
            float2 a3 = __half22float2(reinterpret_cast<const __half2&>(r3.x));
            float2 b3 = __half22float2(reinterpret_cast<const __half2&>(r3.y));
            acc.x = fmaf(v0, a0.x, acc.x);
            acc.y = fmaf(v0, a0.y, acc.y);
            acc.z = fmaf(v0, b0.x, acc.z);
            acc.w = fmaf(v0, b0.y, acc.w);
            acc.x = fmaf(v1, a1.x, acc.x);
            acc.y = fmaf(v1, a1.y, acc.y);
            acc.z = fmaf(v1, b1.x, acc.z);
            acc.w = fmaf(v1, b1.y, acc.w);
            acc.x = fmaf(v2, a2.x, acc.x);
            acc.y = fmaf(v2, a2.y, acc.y);
            acc.z = fmaf(v2, b2.x, acc.z);
            acc.w = fmaf(v2, b2.y, acc.w);
            acc.x = fmaf(v3, a3.x, acc.x);
            acc.y = fmaf(v3, a3.y, acc.y);
            acc.z = fmaf(v3, b3.x, acc.z);
            acc.w = fmaf(v3, b3.y, acc.w);
        }
    }

    float nrm = g_norm[w];
    float4 bv = reinterpret_cast<const float4*>(bias)[lane];
    float4 o;
    o.x = fmaxf(fmaf(acc.x, nrm, bv.x), 0.f);
    o.y = fmaxf(fmaf(acc.y, nrm, bv.y), 0.f);
    o.z = fmaxf(fmaf(acc.z, nrm, bv.z), 0.f);
    o.w = fmaxf(fmaf(acc.w, nrm, bv.w), 0.f);
    reinterpret_cast<float4*>(out)[(size_t)w * 32 + lane] = o;
}

// ---------------------------------------------------------------------------
extern "C" void kernel_launch(void* const* d_in, const int* in_sizes, int n_in,
                              void* d_out, int out_size) {
    const float* x  = (const float*)d_in[0];   // [B,N,D]
    const float* W  = (const float*)d_in[1];   // [D,D]
    const float* bb = (const float*)d_in[2];   // [D]
    const int*   eb = (const int*)d_in[3];     // [E]
    const int*   er = (const int*)d_in[4];     // [E]
    const int*   ec = (const int*)d_in[5];     // [E]
    const float* ev = (const float*)d_in[6];   // [E]
    int E = in_sizes[3];

    float* out = (float*)d_out;

    k_gemm_hist<<<GEMM_BLOCKS + HIST_BLOCKS, 256>>>(x, W, eb, er, ev, E);
    k_scanA<<<SCAN_BLOCKS, 256>>>();
    k_scanBC<<<SCAN_BLOCKS, 256>>>();
    k_scatter<<<(E + 255) / 256, 256>>>(eb, er, ec, ev, E);
    k_spmm<<<(BNc * 32) / 256, 256>>>(bb, out);
}